// round 11
// baseline (speedup 1.0000x reference)
#include <cuda_runtime.h>
#include <cuda_fp16.h>
#include <math.h>
#include <stdint.h>

#define B 64
#define L 256
#define H 1024
#define P 64
#define A 512
#define T 8
#define F (H + 2 * P)   // 1152
#define M_TOT (B * L)   // 16384

// ---------------- scratch (device globals; no allocation allowed) ----------
__device__ float g_ef[B * 4 * H];            // entity_features [B, 4H]
__device__ float g_dense_ent[B * A];         // [B, A]
__device__ float g_vu_part[4][B * L];        // vu partials (per n-quarter)
__device__ float g_zp[8][B * H];             // z partials (split-L x8)
__device__ __half g_wp_h[A * F];             // W_pos^T fp16 [A, F]

// ---------------- helpers --------------------------------------------------
__device__ __forceinline__ uint32_t smem_u32(const void* p) {
    uint32_t a;
    asm("{ .reg .u64 t; cvta.to.shared.u64 t, %1; cvt.u32.u64 %0, t; }" : "=r"(a) : "l"(p));
    return a;
}

#define CP_ASYNC16(smem, gmem) \
    asm volatile("cp.async.cg.shared.global [%0], [%1], 16;" :: "r"(smem), "l"(gmem))
#define CP_COMMIT() asm volatile("cp.async.commit_group;" ::: "memory")
#define CP_WAIT1()  asm volatile("cp.async.wait_group 1;" ::: "memory")
#define CP_WAIT0()  asm volatile("cp.async.wait_group 0;" ::: "memory")

#define LDSM4(r0, r1, r2, r3, addr) \
    asm volatile("ldmatrix.sync.aligned.m8n8.x4.shared.b16 {%0,%1,%2,%3}, [%4];" \
        : "=r"(r0), "=r"(r1), "=r"(r2), "=r"(r3) : "r"(addr))

#define MMA16816(d, a, bb) \
    asm volatile("mma.sync.aligned.m16n8k16.row.col.f32.f16.f16.f32 " \
        "{%0,%1,%2,%3}, {%4,%5,%6,%7}, {%8,%9}, {%0,%1,%2,%3};" \
        : "+f"((d)[0]), "+f"((d)[1]), "+f"((d)[2]), "+f"((d)[3]) \
        : "r"((a)[0]), "r"((a)[1]), "r"((a)[2]), "r"((a)[3]), "r"((bb)[0]), "r"((bb)[1]))

// ---------------------------------------------------------------------------
// K_PREP: fused W_pos^T->fp16 + entity prep (+ zero accumulators).
// grid = 576 + 64 = 640 CTAs; 256 threads.
// ---------------------------------------------------------------------------
#define NB_WP  ((A / 32) * (F / 32))   // 576
#define NB_ENT B

__global__ void __launch_bounds__(256)
k_prep(const float* __restrict__ wh,
       const float* __restrict__ Wp,
       const int* __restrict__ e1_end,
       const int* __restrict__ e2_end,
       const float* __restrict__ te) {
    const int bx = blockIdx.x;
    const int tid = threadIdx.x;

    if (bx < NB_WP) {
        __shared__ float tile[32][33];
        const int a0 = (bx & 15) * 32;
        const int f0 = (bx >> 4) * 32;
        const int tx = tid & 31;
        const int ty = tid >> 5;
#pragma unroll
        for (int i = 0; i < 4; i++) {
            int f = ty + i * 8;
            tile[f][tx] = Wp[(size_t)(f0 + f) * A + a0 + tx];
        }
        __syncthreads();
#pragma unroll
        for (int i = 0; i < 4; i++) {
            int ar = ty + i * 8;
            g_wp_h[(size_t)(a0 + ar) * F + f0 + tx] = __float2half_rn(tile[tx][ar]);
        }
        return;
    }

    {
        const int b = bx - NB_WP;
        const int lane = tid & 31;
        const int wid = tid >> 5;

        __shared__ float wsum[8][16];
        __shared__ float scores[16];
        __shared__ float alpha[2][T];

        const float* h1 = wh + ((size_t)b * L + e1_end[b]) * H;
        const float* h2 = wh + ((size_t)b * L + e2_end[b]) * H;

        float s[16];
#pragma unroll
        for (int i = 0; i < 16; i++) s[i] = 0.f;
        for (int h = tid; h < H; h += 256) {
            float v1 = h1[h], v2 = h2[h];
#pragma unroll
            for (int t = 0; t < T; t++) {
                float c = te[t * H + h];
                s[t] += v1 * c;
                s[8 + t] += v2 * c;
            }
        }
#pragma unroll
        for (int off = 16; off; off >>= 1)
#pragma unroll
            for (int i = 0; i < 16; i++) s[i] += __shfl_xor_sync(0xffffffffu, s[i], off);
        if (lane == 0)
#pragma unroll
            for (int i = 0; i < 16; i++) wsum[wid][i] = s[i];
        __syncthreads();
        if (tid < 16) {
            float tot = 0.f;
#pragma unroll
            for (int w = 0; w < 8; w++) tot += wsum[w][tid];
            scores[tid] = tot;
        }
        __syncthreads();
        if (tid < 2) {
            const float* sc = scores + tid * 8;
            float m = -1e30f;
#pragma unroll
            for (int i = 0; i < T; i++) m = fmaxf(m, sc[i]);
            float sum = 0.f;
            float e[T];
#pragma unroll
            for (int i = 0; i < T; i++) { e[i] = expf(sc[i] - m); sum += e[i]; }
            float inv = 1.f / sum;
#pragma unroll
            for (int i = 0; i < T; i++) alpha[tid][i] = e[i] * inv;
        }
        __syncthreads();

        float* ef = g_ef + (size_t)b * 4 * H;
        for (int h = tid; h < H; h += 256) {
            float t1 = 0.f, t2 = 0.f;
#pragma unroll
            for (int t = 0; t < T; t++) {
                float c = te[t * H + h];
                t1 += alpha[0][t] * c;
                t2 += alpha[1][t] * c;
            }
            ef[h]         = h1[h];
            ef[H + h]     = t1;
            ef[2 * H + h] = h2[h];
            ef[3 * H + h] = t2;
        }

#pragma unroll
        for (int q = 0; q < 4; q++) g_vu_part[q][b * L + tid] = 0.f;
        g_dense_ent[b * A + tid] = 0.f;
        g_dense_ent[b * A + 256 + tid] = 0.f;
    }
}

// ---------------------------------------------------------------------------
// K2: dense_ent = ef[B,4H] @ W_ent[4H,A]; burst then compute.
// grid = (8 a-tiles of 64, 32 k-splits of 128) = 256 CTAs; 256 threads.
// ---------------------------------------------------------------------------
__global__ void __launch_bounds__(256)
k2_dense_ent(const float* __restrict__ W_ent) {
    __shared__ float sE[64][132];   // [b][k]
    __shared__ float sW[128][68];   // [k][a]

    const int a0 = blockIdx.x * 64;
    const int k0 = blockIdx.y * 128;
    const int tid = threadIdx.x;

#pragma unroll
    for (int j = 0; j < 8; j++) {
        int id = tid + j * 256;
        int r = id >> 5, c4 = (id & 31) * 4;
        CP_ASYNC16(smem_u32(&sE[r][c4]), g_ef + (size_t)r * (4 * H) + k0 + c4);
    }
#pragma unroll
    for (int j = 0; j < 8; j++) {
        int id = tid + j * 256;
        int r = id >> 4, c4 = (id & 15) * 4;
        CP_ASYNC16(smem_u32(&sW[r][c4]), W_ent + (size_t)(k0 + r) * A + a0 + c4);
    }
    CP_COMMIT();
    CP_WAIT0();
    __syncthreads();

    const int tx = tid & 15;
    const int ty = tid >> 4;
    float acc[4][4];
#pragma unroll
    for (int r = 0; r < 4; r++)
#pragma unroll
        for (int c = 0; c < 4; c++) acc[r][c] = 0.f;

#pragma unroll 8
    for (int kt = 0; kt < 128; kt++) {
        float4 w = *(const float4*)&sW[kt][tx * 4];
        float wv[4] = {w.x, w.y, w.z, w.w};
#pragma unroll
        for (int r = 0; r < 4; r++) {
            float e = sE[ty * 4 + r][kt];
#pragma unroll
            for (int c = 0; c < 4; c++) acc[r][c] += e * wv[c];
        }
    }
#pragma unroll
    for (int r = 0; r < 4; r++)
#pragma unroll
        for (int c = 0; c < 4; c++)
            atomicAdd(&g_dense_ent[(ty * 4 + r) * A + a0 + tx * 4 + c], acc[r][c]);
}

// ---------------------------------------------------------------------------
// K3: mma.sync fused GEMM with ON-THE-FLY fp32->fp16 A conversion.
// A: LDG fp32 (wh / pe1 / pe2) -> regs -> fp16 STS (2-buffer).
// B: 3-stage cp.async from g_wp_h.
// CTA 128(M) x 128(N), K=1152 in 18 chunks of 64; 2 CTAs/SM.
// grid = (4, 128); 256 threads = 8 warps (2m x 4n), warp tile 64x32.
// ---------------------------------------------------------------------------
#define KT      64
#define PADK    72                      // halves per SMEM row (144 B)
#define A_SZ    (128 * PADK * 2)        // 18432 B per A buffer
#define B_SZ    (128 * PADK * 2)        // 18432 B per B stage
#define OFF_A0  0
#define OFF_A1  (A_SZ)
#define OFF_B   (2 * A_SZ)
#define K3_DSMEM (2 * A_SZ + 3 * B_SZ)  // 92160 B
#define NKCH    (F / KT)                // 18

__global__ void __launch_bounds__(256, 2)
k3_main(const float* __restrict__ v,
        const float* __restrict__ wh,
        const float* __restrict__ pe1,
        const float* __restrict__ pe2) {
    extern __shared__ char dsm[];
    __shared__ float sv[128];

    const int n0 = blockIdx.x * 128;
    const int m0 = blockIdx.y * 128;
    const int b  = blockIdx.y >> 1;
    const int l0 = (blockIdx.y & 1) * 128;
    const int tid = threadIdx.x;
    const int lane = tid & 31;
    const int wid = tid >> 5;
    const int wm = wid >> 2;     // 0..1, m-offset 64
    const int wn = wid & 3;      // 0..3, n-offset 32

    if (tid < 128) sv[tid] = v[n0 + tid];
    const uint32_t sbase = smem_u32(dsm);

    // ---- A geometry: 2 threads/row, 32 floats each (two 16-float halves) --
    const int arow  = tid >> 1;            // 0..127
    const int acol0 = (tid & 1) * 32;      // 0 or 32

    auto load_A = [&](int t, int half, float4* r4) {
        const float* src; int stride, coff;
        if (t < 16)      { src = wh;  stride = H; coff = t * KT; }
        else if (t == 16){ src = pe1; stride = P; coff = 0; }
        else             { src = pe2; stride = P; coff = 0; }
        const float* p = src + (size_t)(m0 + arow) * stride + coff + acol0 + half * 16;
#pragma unroll
        for (int j = 0; j < 4; j++) r4[j] = *(const float4*)(p + j * 4);
    };
    auto store_A = [&](int t, int half, const float4* r4) {
        char* abuf = dsm + ((t & 1) ? OFF_A1 : OFF_A0);
        const int base = arow * (PADK * 2) + (acol0 + half * 16) * 2;
#pragma unroll
        for (int j = 0; j < 4; j++) {
            __half2 h0 = __halves2half2(__float2half_rn(r4[j].x), __float2half_rn(r4[j].y));
            __half2 h1 = __halves2half2(__float2half_rn(r4[j].z), __float2half_rn(r4[j].w));
            *(__half2*)(abuf + base + j * 8)     = h0;
            *(__half2*)(abuf + base + j * 8 + 4) = h1;
        }
    };

    // ---- B geometry: cp.async from g_wp_h ----
    const int rr   = tid >> 3;          // 0..31
    const int ch8  = (tid & 7) * 8;
    const int ch16 = (tid & 7) * 16;
    const __half* gpB = g_wp_h + (size_t)n0 * F + ch8;
    auto load_B = [&](int t, int stg) {
        const int f0 = t * KT;
        const uint32_t sb = sbase + OFF_B + stg * B_SZ;
#pragma unroll
        for (int j = 0; j < 4; j++) {
            int r = rr + j * 32;
            CP_ASYNC16(sb + r * (PADK * 2) + ch16, gpB + (size_t)r * F + f0);
        }
    };

    float acc[4][4][4];
#pragma unroll
    for (int mt = 0; mt < 4; mt++)
#pragma unroll
        for (int nt = 0; nt < 4; nt++)
#pragma unroll
            for (int i = 0; i < 4; i++) acc[mt][nt][i] = 0.f;

    // ---- prologue ----
    {
        float4 r4[4];
        load_A(0, 0, r4); store_A(0, 0, r4);
        load_A(0, 1, r4); store_A(0, 1, r4);
    }
    load_B(0, 0); CP_COMMIT();
    load_B(1, 1); CP_COMMIT();

    auto compute_kts = [&](uint32_t stA, uint32_t stB, int kt0, int kt1) {
#pragma unroll
        for (int kt = kt0; kt < kt1; kt++) {
            uint32_t ah[4][4];
            const int acol = kt * 16 + ((lane >> 4) << 3);
#pragma unroll
            for (int mt = 0; mt < 4; mt++) {
                int row = wm * 64 + mt * 16 + (lane & 15);
                LDSM4(ah[mt][0], ah[mt][1], ah[mt][2], ah[mt][3],
                      stA + row * (PADK * 2) + acol * 2);
            }
            const int bcol = kt * 16 + ((lane & 8) ? 8 : 0);
            const int brow_in = (lane & 7) + ((lane & 16) ? 8 : 0);
#pragma unroll
            for (int pr = 0; pr < 2; pr++) {
                int row = wn * 32 + pr * 16 + brow_in;
                uint32_t bd = stB + row * (PADK * 2) + bcol * 2;
                uint32_t b0[2], b1[2];
                uint32_t r0, r1, r2, r3;
                LDSM4(r0, r1, r2, r3, bd);
                b0[0] = r0; b0[1] = r1; b1[0] = r2; b1[1] = r3;
#pragma unroll
                for (int mt = 0; mt < 4; mt++) {
                    MMA16816(acc[mt][pr * 2],     ah[mt], b0);
                    MMA16816(acc[mt][pr * 2 + 1], ah[mt], b1);
                }
            }
        }
    };

    for (int t = 0; t < NKCH; t++) {
        if (t + 1 < NKCH) CP_WAIT1(); else CP_WAIT0();
        __syncthreads();

        const uint32_t stA = sbase + ((t & 1) ? OFF_A1 : OFF_A0);
        const uint32_t stB = sbase + OFF_B + (t % 3) * B_SZ;
        const bool hasNext = (t + 1 < NKCH);

        float4 pre[4];
        if (hasNext) load_A(t + 1, 0, pre);
        compute_kts(stA, stB, 0, 2);
        if (hasNext) { store_A(t + 1, 0, pre); load_A(t + 1, 1, pre); }
        compute_kts(stA, stB, 2, 4);
        if (hasNext) store_A(t + 1, 1, pre);

        if (t + 2 < NKCH) { load_B(t + 2, (t + 2) % 3); CP_COMMIT(); }
    }

    // ---- epilogue: tanh(acc + ent) . v, quad-reduce, atomic into quarter ---
    const int quarter = blockIdx.x;
    const int halfA = quarter >> 1;
#pragma unroll
    for (int mt = 0; mt < 4; mt++) {
#pragma unroll
        for (int h = 0; h < 2; h++) {
            const int l = l0 + wm * 64 + mt * 16 + (lane >> 2) + h * 8;
            const float e = g_dense_ent[b * A + 2 * l + halfA];
            float part = 0.f;
#pragma unroll
            for (int nt = 0; nt < 4; nt++) {
                int a = wn * 32 + nt * 8 + 2 * (lane & 3);
                part += sv[a]     * tanhf(acc[mt][nt][2 * h]     + e);
                part += sv[a + 1] * tanhf(acc[mt][nt][2 * h + 1] + e);
            }
            part += __shfl_xor_sync(0xffffffffu, part, 1);
            part += __shfl_xor_sync(0xffffffffu, part, 2);
            if ((lane & 3) == 0) atomicAdd(&g_vu_part[quarter][b * L + l], part);
        }
    }
}

// ---------------------------------------------------------------------------
// K4: softmax over L + partial z from fp32 wh. grid = (B, 8); 256 threads.
// ---------------------------------------------------------------------------
__global__ void __launch_bounds__(256)
k4_softmax_zp(const float* __restrict__ wh) {
    const int b = blockIdx.x;
    const int lq = blockIdx.y;
    const int tid = threadIdx.x;
    const int lane = tid & 31;
    const int wid = tid >> 5;

    __shared__ float sa[L];
    __shared__ float red[8];

    float vu = (g_vu_part[0][b * L + tid] + g_vu_part[1][b * L + tid])
             + (g_vu_part[2][b * L + tid] + g_vu_part[3][b * L + tid]);

    float m = vu;
#pragma unroll
    for (int off = 16; off; off >>= 1) m = fmaxf(m, __shfl_xor_sync(0xffffffffu, m, off));
    if (lane == 0) red[wid] = m;
    __syncthreads();
    if (tid < 8) {
        float mm = red[tid];
#pragma unroll
        for (int off = 4; off; off >>= 1) mm = fmaxf(mm, __shfl_xor_sync(0xffu, mm, off));
        if (tid == 0) red[0] = mm;
    }
    __syncthreads();
    const float mv = red[0];
    __syncthreads();

    float ex = expf(vu - mv);
    float ssum = ex;
#pragma unroll
    for (int off = 16; off; off >>= 1) ssum += __shfl_xor_sync(0xffffffffu, ssum, off);
    if (lane == 0) red[wid] = ssum;
    __syncthreads();
    if (tid < 8) {
        float ss = red[tid];
#pragma unroll
        for (int off = 4; off; off >>= 1) ss += __shfl_xor_sync(0xffu, ss, off);
        if (tid == 0) red[0] = ss;
    }
    __syncthreads();
    const float inv = 1.f / red[0];
    sa[tid] = ex * inv;
    __syncthreads();

    const int h4 = tid * 4;
    const float* base = wh + ((size_t)b * L + lq * 32) * H + h4;
    float ax = 0.f, ay = 0.f, az = 0.f, aw = 0.f;
#pragma unroll
    for (int l2 = 0; l2 < 32; l2++) {
        float4 x = *(const float4*)(base + (size_t)l2 * H);
        float s = sa[lq * 32 + l2];
        ax += s * x.x; ay += s * x.y; az += s * x.z; aw += s * x.w;
    }
    float4 o = {ax, ay, az, aw};
    *(float4*)(&g_zp[lq][b * H + h4]) = o;
}

// ---------------------------------------------------------------------------
// K5: z = sum of 8 partials. 64 blocks x 256 threads, float4 per thread.
// ---------------------------------------------------------------------------
__global__ void k5_combine(float* __restrict__ z) {
    const int i4 = (blockIdx.x * 256 + threadIdx.x) * 4;
    float4 o = {0.f, 0.f, 0.f, 0.f};
#pragma unroll
    for (int p = 0; p < 8; p++) {
        float4 a = *(const float4*)&g_zp[p][i4];
        o.x += a.x; o.y += a.y; o.z += a.z; o.w += a.w;
    }
    *(float4*)(z + i4) = o;
}

// ---------------------------------------------------------------------------
extern "C" void kernel_launch(void* const* d_in, const int* in_sizes, int n_in,
                              void* d_out, int out_size) {
    const float* wh   = (const float*)d_in[0];
    const float* pe1  = (const float*)d_in[1];
    const float* pe2  = (const float*)d_in[2];
    const int*   e1e  = (const int*)d_in[3];
    const int*   e2e  = (const int*)d_in[4];
    const float* te   = (const float*)d_in[5];
    const float* Wp   = (const float*)d_in[6];
    const float* We   = (const float*)d_in[7];
    const float* v    = (const float*)d_in[8];
    float* z = (float*)d_out;

    cudaFuncSetAttribute(k3_main, cudaFuncAttributeMaxDynamicSharedMemorySize, K3_DSMEM);

    k_prep<<<NB_WP + NB_ENT, 256>>>(wh, Wp, e1e, e2e, te);
    k2_dense_ent<<<dim3(8, 32), 256>>>(We);
    k3_main<<<dim3(4, 128), 256, K3_DSMEM>>>(v, wh, pe1, pe2);
    k4_softmax_zp<<<dim3(B, 8), 256>>>(wh);
    k5_combine<<<64, 256>>>(z);
}

// round 12
// speedup vs baseline: 1.3771x; 1.3771x over previous
#include <cuda_runtime.h>
#include <cuda_fp16.h>
#include <math.h>
#include <stdint.h>

#define B 64
#define L 256
#define H 1024
#define P 64
#define A 512
#define T 8
#define F (H + 2 * P)   // 1152
#define M_TOT (B * L)   // 16384
#define K_ENT (4 * H)   // 4096

// ---------------- scratch (device globals; no allocation allowed) ----------
__device__ __half g_ef_h[B * K_ENT];         // entity_features fp16 [B, 4H]
__device__ __half g_went_h[A * K_ENT];       // W_ent^T fp16 [A, 4H]
__device__ float g_dense_ent[B * A];         // [B, A]
__device__ float g_vu_part[4][B * L];        // vu partials (per n-quarter)
__device__ float g_zp[8][B * H];             // z partials (split-L x8)
__device__ __half g_pf_h[M_TOT * F];         // pos_features fp16 [M, F]
__device__ __half g_wp_h[A * F];             // W_pos^T fp16 [A, F]

// ---------------- helpers --------------------------------------------------
__device__ __forceinline__ uint32_t smem_u32(const void* p) {
    uint32_t a;
    asm("{ .reg .u64 t; cvta.to.shared.u64 t, %1; cvt.u32.u64 %0, t; }" : "=r"(a) : "l"(p));
    return a;
}

#define CP_ASYNC16(smem, gmem) \
    asm volatile("cp.async.cg.shared.global [%0], [%1], 16;" :: "r"(smem), "l"(gmem))
#define CP_COMMIT() asm volatile("cp.async.commit_group;" ::: "memory")
#define CP_WAIT1()  asm volatile("cp.async.wait_group 1;" ::: "memory")
#define CP_WAIT0()  asm volatile("cp.async.wait_group 0;" ::: "memory")

#define LDSM4(r0, r1, r2, r3, addr) \
    asm volatile("ldmatrix.sync.aligned.m8n8.x4.shared.b16 {%0,%1,%2,%3}, [%4];" \
        : "=r"(r0), "=r"(r1), "=r"(r2), "=r"(r3) : "r"(addr))

#define MMA16816(d, a, bb) \
    asm volatile("mma.sync.aligned.m16n8k16.row.col.f32.f16.f16.f32 " \
        "{%0,%1,%2,%3}, {%4,%5,%6,%7}, {%8,%9}, {%0,%1,%2,%3};" \
        : "+f"((d)[0]), "+f"((d)[1]), "+f"((d)[2]), "+f"((d)[3]) \
        : "r"((a)[0]), "r"((a)[1]), "r"((a)[2]), "r"((a)[3]), "r"((bb)[0]), "r"((bb)[1]))

// ---------------------------------------------------------------------------
// K_PREP: fused pf->fp16, W_pos^T->fp16, W_ent^T->fp16, entity prep.
// grid = 16384 + 576 + 2048 + 64 = 19072 CTAs; 256 threads.
// ---------------------------------------------------------------------------
#define NB_PF  M_TOT
#define NB_WP  ((A / 32) * (F / 32))      // 576
#define NB_WE  ((A / 32) * (K_ENT / 32))  // 2048
#define NB_ENT B

__global__ void __launch_bounds__(256)
k_prep(const float* __restrict__ wh,
       const float* __restrict__ pe1,
       const float* __restrict__ pe2,
       const float* __restrict__ Wp,
       const float* __restrict__ We,
       const int* __restrict__ e1_end,
       const int* __restrict__ e2_end,
       const float* __restrict__ te) {
    const int bx = blockIdx.x;
    const int tid = threadIdx.x;

    if (bx < NB_PF) {
        const int m = bx;
        const float* s0 = wh  + (size_t)m * H;
        const float* s1 = pe1 + (size_t)m * P;
        const float* s2 = pe2 + (size_t)m * P;
        __half* oh = g_pf_h + (size_t)m * F;
        for (int i = tid; i < F / 4; i += 256) {
            int f4 = i * 4;
            float4 x;
            if (f4 < H)            x = *(const float4*)(s0 + f4);
            else if (f4 < H + P)   x = *(const float4*)(s1 + (f4 - H));
            else                   x = *(const float4*)(s2 + (f4 - H - P));
            __half2 hh[2] = {__halves2half2(__float2half_rn(x.x), __float2half_rn(x.y)),
                             __halves2half2(__float2half_rn(x.z), __float2half_rn(x.w))};
            *(uint2*)(oh + f4) = *(uint2*)hh;
        }
        return;
    }

    if (bx < NB_PF + NB_WP) {
        __shared__ float tile[32][33];
        const int t0 = bx - NB_PF;
        const int a0 = (t0 & 15) * 32;
        const int f0 = (t0 >> 4) * 32;
        const int tx = tid & 31;
        const int ty = tid >> 5;
#pragma unroll
        for (int i = 0; i < 4; i++) {
            int f = ty + i * 8;
            tile[f][tx] = Wp[(size_t)(f0 + f) * A + a0 + tx];
        }
        __syncthreads();
#pragma unroll
        for (int i = 0; i < 4; i++) {
            int ar = ty + i * 8;
            g_wp_h[(size_t)(a0 + ar) * F + f0 + tx] = __float2half_rn(tile[tx][ar]);
        }
        return;
    }

    if (bx < NB_PF + NB_WP + NB_WE) {
        __shared__ float tile[32][33];
        const int t0 = bx - NB_PF - NB_WP;
        const int a0 = (t0 & 15) * 32;
        const int k0 = (t0 >> 4) * 32;
        const int tx = tid & 31;
        const int ty = tid >> 5;
#pragma unroll
        for (int i = 0; i < 4; i++) {
            int k = ty + i * 8;
            tile[k][tx] = We[(size_t)(k0 + k) * A + a0 + tx];
        }
        __syncthreads();
#pragma unroll
        for (int i = 0; i < 4; i++) {
            int ar = ty + i * 8;
            g_went_h[(size_t)(a0 + ar) * K_ENT + k0 + tx] = __float2half_rn(tile[tx][ar]);
        }
        return;
    }

    {
        const int b = bx - NB_PF - NB_WP - NB_WE;
        const int lane = tid & 31;
        const int wid = tid >> 5;

        __shared__ float wsum[8][16];
        __shared__ float scores[16];
        __shared__ float alpha[2][T];

        const float* h1 = wh + ((size_t)b * L + e1_end[b]) * H;
        const float* h2 = wh + ((size_t)b * L + e2_end[b]) * H;

        float s[16];
#pragma unroll
        for (int i = 0; i < 16; i++) s[i] = 0.f;
        for (int h = tid; h < H; h += 256) {
            float v1 = h1[h], v2 = h2[h];
#pragma unroll
            for (int t = 0; t < T; t++) {
                float c = te[t * H + h];
                s[t] += v1 * c;
                s[8 + t] += v2 * c;
            }
        }
#pragma unroll
        for (int off = 16; off; off >>= 1)
#pragma unroll
            for (int i = 0; i < 16; i++) s[i] += __shfl_xor_sync(0xffffffffu, s[i], off);
        if (lane == 0)
#pragma unroll
            for (int i = 0; i < 16; i++) wsum[wid][i] = s[i];
        __syncthreads();
        if (tid < 16) {
            float tot = 0.f;
#pragma unroll
            for (int w = 0; w < 8; w++) tot += wsum[w][tid];
            scores[tid] = tot;
        }
        __syncthreads();
        if (tid < 2) {
            const float* sc = scores + tid * 8;
            float m = -1e30f;
#pragma unroll
            for (int i = 0; i < T; i++) m = fmaxf(m, sc[i]);
            float sum = 0.f;
            float e[T];
#pragma unroll
            for (int i = 0; i < T; i++) { e[i] = expf(sc[i] - m); sum += e[i]; }
            float inv = 1.f / sum;
#pragma unroll
            for (int i = 0; i < T; i++) alpha[tid][i] = e[i] * inv;
        }
        __syncthreads();

        __half* ef = g_ef_h + (size_t)b * K_ENT;
        for (int h = tid; h < H; h += 256) {
            float t1 = 0.f, t2 = 0.f;
#pragma unroll
            for (int t = 0; t < T; t++) {
                float c = te[t * H + h];
                t1 += alpha[0][t] * c;
                t2 += alpha[1][t] * c;
            }
            ef[h]         = __float2half_rn(h1[h]);
            ef[H + h]     = __float2half_rn(t1);
            ef[2 * H + h] = __float2half_rn(h2[h]);
            ef[3 * H + h] = __float2half_rn(t2);
        }

#pragma unroll
        for (int q = 0; q < 4; q++) g_vu_part[q][b * L + tid] = 0.f;
        g_dense_ent[b * A + tid] = 0.f;
        g_dense_ent[b * A + 256 + tid] = 0.f;
    }
}

// ---------------------------------------------------------------------------
// K2 v4 (HMMA): dense_ent = ef[64,4096] @ W_ent[4096,512], split-K=32.
// grid = (4 n-tiles of 128, 32 k-splits of 128) = 128 CTAs; 256 threads.
// CTA tile 64(M) x 128(N) x 128(K); 8 warps (2m x 4n), warp tile 32x32.
// ---------------------------------------------------------------------------
#define PADK2   136                      // halves per SMEM row (272 B)
#define K2_ASZ  (64 * PADK2 * 2)         // 17408 B
__global__ void __launch_bounds__(256)
k2_dense_ent() {
    __shared__ __align__(16) __half sA[64 * PADK2];
    __shared__ __align__(16) __half sB[128 * PADK2];

    const int n0 = blockIdx.x * 128;
    const int k0 = blockIdx.y * 128;
    const int tid = threadIdx.x;
    const int lane = tid & 31;
    const int wid = tid >> 5;
    const int wm = wid >> 2;     // 0..1, m-offset 32
    const int wn = wid & 3;      // 0..3, n-offset 32

    const uint32_t sa = smem_u32(sA);
    const uint32_t sb = smem_u32(sB);

    // A: 64 rows x 256 B = 1024 chunks; B: 128 rows x 256 B = 2048 chunks
#pragma unroll
    for (int j = 0; j < 4; j++) {
        int id = tid + j * 256;
        int r = id >> 4, ch = id & 15;
        CP_ASYNC16(sa + r * (PADK2 * 2) + ch * 16,
                   g_ef_h + (size_t)r * K_ENT + k0 + ch * 8);
    }
#pragma unroll
    for (int j = 0; j < 8; j++) {
        int id = tid + j * 256;
        int r = id >> 4, ch = id & 15;
        CP_ASYNC16(sb + r * (PADK2 * 2) + ch * 16,
                   g_went_h + (size_t)(n0 + r) * K_ENT + k0 + ch * 8);
    }
    CP_COMMIT();
    CP_WAIT0();
    __syncthreads();

    float acc[2][4][4];
#pragma unroll
    for (int mt = 0; mt < 2; mt++)
#pragma unroll
        for (int nt = 0; nt < 4; nt++)
#pragma unroll
            for (int i = 0; i < 4; i++) acc[mt][nt][i] = 0.f;

#pragma unroll
    for (int kt = 0; kt < 8; kt++) {
        uint32_t ah[2][4];
        const int acol = kt * 16 + ((lane >> 4) << 3);
#pragma unroll
        for (int mt = 0; mt < 2; mt++) {
            int row = wm * 32 + mt * 16 + (lane & 15);
            LDSM4(ah[mt][0], ah[mt][1], ah[mt][2], ah[mt][3],
                  sa + row * (PADK2 * 2) + acol * 2);
        }
        const int bcol = kt * 16 + ((lane & 8) ? 8 : 0);
        const int brow_in = (lane & 7) + ((lane & 16) ? 8 : 0);
#pragma unroll
        for (int pr = 0; pr < 2; pr++) {
            int row = wn * 32 + pr * 16 + brow_in;
            uint32_t bd = sb + row * (PADK2 * 2) + bcol * 2;
            uint32_t b0[2], b1[2];
            uint32_t r0, r1, r2, r3;
            LDSM4(r0, r1, r2, r3, bd);
            b0[0] = r0; b0[1] = r1; b1[0] = r2; b1[1] = r3;
#pragma unroll
            for (int mt = 0; mt < 2; mt++) {
                MMA16816(acc[mt][pr * 2],     ah[mt], b0);
                MMA16816(acc[mt][pr * 2 + 1], ah[mt], b1);
            }
        }
    }

#pragma unroll
    for (int mt = 0; mt < 2; mt++)
#pragma unroll
        for (int h = 0; h < 2; h++) {
            const int bb = wm * 32 + mt * 16 + (lane >> 2) + h * 8;
#pragma unroll
            for (int nt = 0; nt < 4; nt++) {
                int a = n0 + wn * 32 + nt * 8 + 2 * (lane & 3);
                atomicAdd(&g_dense_ent[bb * A + a],     acc[mt][nt][2 * h]);
                atomicAdd(&g_dense_ent[bb * A + a + 1], acc[mt][nt][2 * h + 1]);
            }
        }
}

// ---------------------------------------------------------------------------
// K3 (R10 best): mma.sync fused GEMM (fp16 x fp16, fp32 accum) + epilogue.
// CTA 128(M) x 128(N), K=1152 in 18 chunks of 64; 3-stage cp.async; 2 CTAs/SM.
// grid = (4, 128); 256 threads = 8 warps (2m x 4n), warp tile 64x32.
// ---------------------------------------------------------------------------
#define KT      64
#define PADK    72                      // halves per SMEM row (144 B)
#define A_SZ    (128 * PADK * 2)        // 18432 B
#define B_SZ    (128 * PADK * 2)        // 18432 B
#define OFF_A   0
#define OFF_B   (A_SZ)
#define STG_SZ  (A_SZ + B_SZ)           // 36864 B
#define NSTG    3
#define K3_DSMEM (NSTG * STG_SZ)        // 110592 B
#define NKCH    (F / KT)                // 18

__global__ void __launch_bounds__(256, 2)
k3_main(const float* __restrict__ v) {
    extern __shared__ char dsm[];
    __shared__ float sv[128];

    const int n0 = blockIdx.x * 128;
    const int m0 = blockIdx.y * 128;
    const int b  = blockIdx.y >> 1;
    const int l0 = (blockIdx.y & 1) * 128;
    const int tid = threadIdx.x;
    const int lane = tid & 31;
    const int wid = tid >> 5;
    const int wm = wid >> 2;     // 0..1, m-offset 64
    const int wn = wid & 3;      // 0..3, n-offset 32

    if (tid < 128) sv[tid] = v[n0 + tid];
    const uint32_t sbase = smem_u32(dsm);

    const int rr   = tid >> 3;          // 0..31
    const int ch8  = (tid & 7) * 8;
    const int ch16 = (tid & 7) * 16;
    const __half* gp0 = g_pf_h + (size_t)m0 * F + ch8;
    const __half* gp2 = g_wp_h + (size_t)n0 * F + ch8;

    auto load_stage = [&](int t, int stg) {
        const int f0 = t * KT;
        const uint32_t sb = sbase + stg * STG_SZ;
#pragma unroll
        for (int j = 0; j < 4; j++) {
            int r = rr + j * 32;
            CP_ASYNC16(sb + OFF_A + r * (PADK * 2) + ch16, gp0 + (size_t)r * F + f0);
        }
#pragma unroll
        for (int j = 0; j < 4; j++) {
            int r = rr + j * 32;
            CP_ASYNC16(sb + OFF_B + r * (PADK * 2) + ch16, gp2 + (size_t)r * F + f0);
        }
    };

    float acc[4][4][4];
#pragma unroll
    for (int mt = 0; mt < 4; mt++)
#pragma unroll
        for (int nt = 0; nt < 4; nt++)
#pragma unroll
            for (int i = 0; i < 4; i++) acc[mt][nt][i] = 0.f;

    load_stage(0, 0); CP_COMMIT();
    load_stage(1, 1); CP_COMMIT();

    for (int t = 0; t < NKCH; t++) {
        const int s = t % NSTG;
        if (t + 1 < NKCH) CP_WAIT1(); else CP_WAIT0();
        __syncthreads();

        const uint32_t st = sbase + s * STG_SZ;
#pragma unroll
        for (int kt = 0; kt < 4; kt++) {
            uint32_t ah[4][4];
            const int acol = kt * 16 + ((lane >> 4) << 3);
#pragma unroll
            for (int mt = 0; mt < 4; mt++) {
                int row = wm * 64 + mt * 16 + (lane & 15);
                LDSM4(ah[mt][0], ah[mt][1], ah[mt][2], ah[mt][3],
                      st + OFF_A + row * (PADK * 2) + acol * 2);
            }
            const int bcol = kt * 16 + ((lane & 8) ? 8 : 0);
            const int brow_in = (lane & 7) + ((lane & 16) ? 8 : 0);
#pragma unroll
            for (int pr = 0; pr < 2; pr++) {
                int row = wn * 32 + pr * 16 + brow_in;
                uint32_t bd = st + OFF_B + row * (PADK * 2) + bcol * 2;
                uint32_t b0[2], b1[2];
                uint32_t r0, r1, r2, r3;
                LDSM4(r0, r1, r2, r3, bd);
                b0[0] = r0; b0[1] = r1; b1[0] = r2; b1[1] = r3;
#pragma unroll
                for (int mt = 0; mt < 4; mt++) {
                    MMA16816(acc[mt][pr * 2],     ah[mt], b0);
                    MMA16816(acc[mt][pr * 2 + 1], ah[mt], b1);
                }
            }
        }

        if (t + 2 < NKCH) { load_stage(t + 2, (t + 2) % NSTG); CP_COMMIT(); }
    }

    const int quarter = blockIdx.x;
    const int halfA = quarter >> 1;
#pragma unroll
    for (int mt = 0; mt < 4; mt++) {
#pragma unroll
        for (int h = 0; h < 2; h++) {
            const int l = l0 + wm * 64 + mt * 16 + (lane >> 2) + h * 8;
            const float e = g_dense_ent[b * A + 2 * l + halfA];
            float part = 0.f;
#pragma unroll
            for (int nt = 0; nt < 4; nt++) {
                int a = wn * 32 + nt * 8 + 2 * (lane & 3);
                part += sv[a]     * tanhf(acc[mt][nt][2 * h]     + e);
                part += sv[a + 1] * tanhf(acc[mt][nt][2 * h + 1] + e);
            }
            part += __shfl_xor_sync(0xffffffffu, part, 1);
            part += __shfl_xor_sync(0xffffffffu, part, 2);
            if ((lane & 3) == 0) atomicAdd(&g_vu_part[quarter][b * L + l], part);
        }
    }
}

// ---------------------------------------------------------------------------
// K4: softmax over L + partial z from fp16 pf plane. grid=(B,8); 256 threads.
// ---------------------------------------------------------------------------
__global__ void __launch_bounds__(256)
k4_softmax_zp() {
    const int b = blockIdx.x;
    const int lq = blockIdx.y;
    const int tid = threadIdx.x;
    const int lane = tid & 31;
    const int wid = tid >> 5;

    __shared__ float sa[L];
    __shared__ float red[8];

    float vu = (g_vu_part[0][b * L + tid] + g_vu_part[1][b * L + tid])
             + (g_vu_part[2][b * L + tid] + g_vu_part[3][b * L + tid]);

    float m = vu;
#pragma unroll
    for (int off = 16; off; off >>= 1) m = fmaxf(m, __shfl_xor_sync(0xffffffffu, m, off));
    if (lane == 0) red[wid] = m;
    __syncthreads();
    if (tid < 8) {
        float mm = red[tid];
#pragma unroll
        for (int off = 4; off; off >>= 1) mm = fmaxf(mm, __shfl_xor_sync(0xffu, mm, off));
        if (tid == 0) red[0] = mm;
    }
    __syncthreads();
    const float mv = red[0];
    __syncthreads();

    float ex = expf(vu - mv);
    float ssum = ex;
#pragma unroll
    for (int off = 16; off; off >>= 1) ssum += __shfl_xor_sync(0xffffffffu, ssum, off);
    if (lane == 0) red[wid] = ssum;
    __syncthreads();
    if (tid < 8) {
        float ss = red[tid];
#pragma unroll
        for (int off = 4; off; off >>= 1) ss += __shfl_xor_sync(0xffu, ss, off);
        if (tid == 0) red[0] = ss;
    }
    __syncthreads();
    const float inv = 1.f / red[0];
    sa[tid] = ex * inv;
    __syncthreads();

    const int h4 = tid * 4;
    const __half* base = g_pf_h + ((size_t)b * L + lq * 32) * F + h4;
    float ax = 0.f, ay = 0.f, az = 0.f, aw = 0.f;
#pragma unroll
    for (int l2 = 0; l2 < 32; l2++) {
        uint2 raw = *(const uint2*)(base + (size_t)l2 * F);
        __half2 p0 = *(__half2*)&raw.x;
        __half2 p1 = *(__half2*)&raw.y;
        float2 f0 = __half22float2(p0);
        float2 f1 = __half22float2(p1);
        float s = sa[lq * 32 + l2];
        ax += s * f0.x; ay += s * f0.y; az += s * f1.x; aw += s * f1.y;
    }
    float4 o = {ax, ay, az, aw};
    *(float4*)(&g_zp[lq][b * H + h4]) = o;
}

// ---------------------------------------------------------------------------
// K5: z = sum of 8 partials. 64 blocks x 256 threads, float4 per thread.
// ---------------------------------------------------------------------------
__global__ void k5_combine(float* __restrict__ z) {
    const int i4 = (blockIdx.x * 256 + threadIdx.x) * 4;
    float4 o = {0.f, 0.f, 0.f, 0.f};
#pragma unroll
    for (int p = 0; p < 8; p++) {
        float4 a = *(const float4*)&g_zp[p][i4];
        o.x += a.x; o.y += a.y; o.z += a.z; o.w += a.w;
    }
    *(float4*)(z + i4) = o;
}

// ---------------------------------------------------------------------------
extern "C" void kernel_launch(void* const* d_in, const int* in_sizes, int n_in,
                              void* d_out, int out_size) {
    const float* wh   = (const float*)d_in[0];
    const float* pe1  = (const float*)d_in[1];
    const float* pe2  = (const float*)d_in[2];
    const int*   e1e  = (const int*)d_in[3];
    const int*   e2e  = (const int*)d_in[4];
    const float* te   = (const float*)d_in[5];
    const float* Wp   = (const float*)d_in[6];
    const float* We   = (const float*)d_in[7];
    const float* v    = (const float*)d_in[8];
    float* z = (float*)d_out;

    cudaFuncSetAttribute(k3_main, cudaFuncAttributeMaxDynamicSharedMemorySize, K3_DSMEM);

    k_prep<<<NB_PF + NB_WP + NB_WE + NB_ENT, 256>>>(wh, pe1, pe2, Wp, We, e1e, e2e, te);
    k2_dense_ent<<<dim3(4, 32), 256>>>();
    k3_main<<<dim3(4, 128), 256, K3_DSMEM>>>(v);
    k4_softmax_zp<<<dim3(B, 8), 256>>>();
    k5_combine<<<64, 256>>>(z);
}